// round 4
// baseline (speedup 1.0000x reference)
#include <cuda_runtime.h>
#include <math.h>

#define LOG2PI_F 1.83787706640934548356f

// ---------------- device-global scratch (no allocations allowed) ----------------
__device__ float g_Saa[64 * 64];
__device__ float g_Sab[64 * 64];
__device__ float g_Sbb[64 * 64];
__device__ float g_fmu[64];
__device__ float g_fvar[64 * 64];
__device__ float g_fscore;

// ---------------- prep: trans_var = C^T C, split into blocks ----------------
__global__ void prep_kernel(const float* __restrict__ C) {
    int idx = blockIdx.x * blockDim.x + threadIdx.x;
    if (idx >= 128 * 128) return;
    int i = idx >> 7, j = idx & 127;
    float s = 0.f;
#pragma unroll 8
    for (int k = 0; k < 128; k++) s += C[k * 128 + i] * C[k * 128 + j];
    if (i < 64) {
        if (j < 64) g_Saa[i * 64 + j] = s;
        else        g_Sab[i * 64 + (j - 64)] = s;
    } else if (j >= 64) {
        g_Sbb[(i - 64) * 64 + (j - 64)] = s;
    }
}

// ---------------- deferred-scaling Cholesky + forward substitution, 1 sync/column ----
// M: 64x64 (stride 65), lower triangle = SPD matrix. On exit: column k below the
//    diagonal holds the UNSCALED eliminated column c_k; diag holds piv_k = L_kk^2.
//    ldiag[k] = piv_k.
// W: 64x65 (stride 65): cols 0..63 = RHS block, col 64 = RHS vector. On exit row k
//    holds unscaled residuals w_k; true solve value z[k][j] = W[k][j]/sqrt(piv_k).
// Update rule (step k):  X[i][.] -= M[i][k] * (X[k][.] / piv_k)   for i > k.
// TRI=true: RHS block is diag(d) -> stays lower triangular; only cols j<=k + col 64
// have a nonzero row-k entry, so only those columns need updating.
// Two threads per column (halves of the row range) -> 256 threads fully used.
template <bool TRI>
__device__ __forceinline__ void chol64(float* M, float* W, float* ldiag, int tid) {
    const int s = tid >> 1, h = tid & 1;
    for (int k = 0; k < 64; k++) {
        float piv = M[k * 65 + k];          // final after step k-1's sync
        if (tid == 0) ldiag[k] = piv;
        float ip = 1.0f / piv;
        int r = 63 - k;                     // trailing M columns
        int ncols = TRI ? (k + 2) : 65;     // active W columns (incl. vector col)
        if (s < r) {
            int j = k + 1 + s;
            float c = M[j * 65 + k] * ip;
            int mid = (j + 64) >> 1;
            int lo = h ? mid : j;
            int hi = h ? 64 : mid;
#pragma unroll 4
            for (int i = lo; i < hi; i++) M[i * 65 + j] -= M[i * 65 + k] * c;
        } else if (s < r + ncols) {
            int q = s - r;
            int j = (q == ncols - 1) ? 64 : q;
            float wk = W[k * 65 + j] * ip;
            int mid = (k + 65) >> 1;
            int lo = h ? mid : (k + 1);
            int hi = h ? 64 : mid;
#pragma unroll 4
            for (int i = lo; i < hi; i++) W[i * 65 + j] -= M[i * 65 + k] * wk;
        }
        __syncthreads();
    }
}

// ---------------- lower-triangle weighted SYRK: M(lower) = gAdd (+diag dd) - W^T diag(ipv) W
// 4x4 register tiles over the 136 lower tiles of a 16x16 tile grid. No syncs inside.
__device__ __forceinline__ void syrk_lower(float* M, const float* W,
                                           const float* __restrict__ gAdd,
                                           const float* dd, const float* ipv,
                                           int tid, bool tri) {
    if (tid < 136) {
        int ti = (int)((sqrtf(8.f * (float)tid + 1.f) - 1.f) * 0.5f);
        while ((ti + 1) * (ti + 2) / 2 <= tid) ++ti;
        while (ti * (ti + 1) / 2 > tid) --ti;
        int tj = tid - ti * (ti + 1) / 2;
        int i0 = ti * 4, j0 = tj * 4;
        float acc[4][4];
#pragma unroll
        for (int a = 0; a < 4; a++)
#pragma unroll
            for (int b = 0; b < 4; b++) acc[a][b] = 0.f;
        int k0 = tri ? i0 : 0;  // triangular W: rows k < i0 are zero in cols >= i0
        for (int k = k0; k < 64; k++) {
            const float* Wr = W + k * 65;
            float ip = ipv[k];
            float a0 = Wr[i0 + 0] * ip, a1 = Wr[i0 + 1] * ip,
                  a2 = Wr[i0 + 2] * ip, a3 = Wr[i0 + 3] * ip;
            float b0 = Wr[j0 + 0], b1 = Wr[j0 + 1], b2 = Wr[j0 + 2], b3 = Wr[j0 + 3];
            acc[0][0] += a0 * b0; acc[0][1] += a0 * b1; acc[0][2] += a0 * b2; acc[0][3] += a0 * b3;
            acc[1][0] += a1 * b0; acc[1][1] += a1 * b1; acc[1][2] += a1 * b2; acc[1][3] += a1 * b3;
            acc[2][0] += a2 * b0; acc[2][1] += a2 * b1; acc[2][2] += a2 * b2; acc[2][3] += a2 * b3;
            acc[3][0] += a3 * b0; acc[3][1] += a3 * b1; acc[3][2] += a3 * b2; acc[3][3] += a3 * b3;
        }
#pragma unroll
        for (int a = 0; a < 4; a++)
#pragma unroll
            for (int b = 0; b < 4; b++) {
                int i = i0 + a, j = j0 + b;
                if (j <= i) {
                    float v = gAdd[i * 64 + j] - acc[a][b];
                    if (dd && i == j) v += dd[i];
                    M[i * 65 + j] = v;
                }
            }
    }
}

// ---------------- transition phase (also used for the initial integral) ----------------
// On entry: M(lower) = lam = Saa + var_e, me = emission mean (or 0 for init).
// On exit:  M(lower) = var_t, mu = mu_t, score accumulated into *s_acc.
__device__ __forceinline__ void transition_phase(float* M, float* W, float* mu,
                                                 const float* me, float* ldiag,
                                                 float* ipv, float* sred, float* s_acc,
                                                 const float* __restrict__ tmu, int tid) {
    for (int n = tid; n < 4096; n += 256) {
        int i = n >> 6, j = n & 63;
        W[i * 65 + j] = g_Sab[n];
    }
    if (tid < 64) W[tid * 65 + 64] = me[tid] - tmu[tid];
    __syncthreads();
    chol64<false>(M, W, ldiag, tid);
    if (tid < 64) ipv[tid] = 1.0f / ldiag[tid];
    __syncthreads();
    if (tid < 64) {
        float z = W[tid * 65 + 64];
        sred[tid] = __logf(ldiag[tid]) + z * z * ipv[tid];   // logdet + z.z contribution
        float acc = 0.f;
#pragma unroll 4
        for (int k = 0; k < 64; k++)
            acc += W[k * 65 + tid] * W[k * 65 + 64] * ipv[k];
        mu[tid] = tmu[64 + tid] + acc;                        // mu_t = mu_b + U^T z2
    }
    syrk_lower(M, W, g_Sbb, nullptr, ipv, tid, false);        // var_t = Sbb - U^T U
    __syncthreads();
    if (tid < 32) {
        float v = sred[tid] + sred[tid + 32];
#pragma unroll
        for (int o = 16; o; o >>= 1) v += __shfl_down_sync(0xffffffffu, v, o);
        if (tid == 0) *s_acc += -0.5f * (64.f * LOG2PI_F + v);
    }
}

// ---------------- the sequential scan: one persistent CTA ----------------
__global__ void __launch_bounds__(256, 1)
scan_kernel(const int* __restrict__ sentence, const int* __restrict__ slen_p, int slen_fb,
            const float* __restrict__ imu_emb, const float* __restrict__ icho_emb,
            const float* __restrict__ tmu) {
    __shared__ float M[64 * 65];   // work matrix: var -> vs -> chol -> lam -> chol -> var_t
    __shared__ float W[64 * 65];   // RHS block (64 cols) + vector col 64
    __shared__ float mu[64], me[64], mm[64], dd[64];
    __shared__ float ldiag[64], ipv[64], sred[64];
    __shared__ float s_acc;

    int tid = threadIdx.x;
    int slen = slen_p ? slen_p[0] : slen_fb;

    // ---- init: lam0 = Saa + I, me = 0, s_acc = 0 ----
    if (tid == 0) s_acc = 0.f;
    if (tid < 64) me[tid] = 0.f;
    for (int n = tid; n < 4096; n += 256) {
        int i = n >> 6, j = n & 63;
        if (j <= i) M[i * 65 + j] = g_Saa[n] + ((i == j) ? 1.f : 0.f);
    }
    __syncthreads();
    transition_phase(M, W, mu, me, ldiag, ipv, sred, &s_acc, tmu, tid);  // (s0, m0, v0)

    // ---- sequential steps ----
    for (int t = 0; t < slen; t++) {
        // -------- emission --------
        if (tid < 64) {
            int tok = sentence[t];
            mm[tid] = imu_emb[tok * 64 + tid];
            float c = icho_emb[tok * 64 + tid];
            dd[tid] = c * c;
        }
        __syncthreads();
        if (tid < 64) M[tid * 65 + tid] += dd[tid];      // vs = var_prev + diag(d), in place
        for (int n = tid; n < 4096; n += 256) {          // W = diag(d) (cols 0..63)
            int i = n >> 6, j = n & 63;
            W[i * 65 + j] = (i == j) ? dd[i] : 0.f;
        }
        if (tid < 64) W[tid * 65 + 64] = mu[tid] - mm[tid];
        __syncthreads();
        chol64<true>(M, W, ldiag, tid);                  // chol(vs); Y,z unscaled in W
        if (tid < 64) ipv[tid] = 1.0f / ldiag[tid];
        __syncthreads();
        if (tid < 64) {
            float z = W[tid * 65 + 64];
            sred[tid] = __logf(ldiag[tid]) + z * z * ipv[tid];
            float acc = 0.f;
#pragma unroll 4
            for (int k = tid; k < 64; k++)
                acc += W[k * 65 + tid] * W[k * 65 + 64] * ipv[k];
            me[tid] = mm[tid] + acc;                     // mu_e = m + Y^T z
        }
        syrk_lower(M, W, g_Saa, dd, ipv, tid, true);     // lam = Saa + diag(d) - Y^T Y
        __syncthreads();
        if (tid < 32) {
            float v = sred[tid] + sred[tid + 32];
#pragma unroll
            for (int o = 16; o; o >>= 1) v += __shfl_down_sync(0xffffffffu, v, o);
            if (tid == 0) s_acc += -0.5f * (64.f * LOG2PI_F + v);
        }
        // -------- transition --------
        transition_phase(M, W, mu, me, ldiag, ipv, sred, &s_acc, tmu, tid);
    }

    // ---- publish carry ----
    if (tid < 64) g_fmu[tid] = mu[tid];
    for (int n = tid; n < 4096; n += 256) {
        int i = n >> 6, j = n & 63;
        if (j <= i) g_fvar[n] = M[i * 65 + j];
    }
    if (tid == 0) g_fscore = s_acc;
}

// ---------------- decode: 50 independent small Choleskys ----------------
__global__ void decode_kernel(const float* __restrict__ omu, const float* __restrict__ ocho,
                              float* __restrict__ out) {
    __shared__ float M[64 * 65];
    __shared__ float b[64];
    __shared__ float ld[64];
    __shared__ float sred[64];
    int l = blockIdx.x, tid = threadIdx.x;  // 64 threads
    for (int n = tid; n < 4096; n += 64) {
        int i = n >> 6, j = n & 63;
        if (j <= i) {
            float v = g_fvar[n];
            if (i == j) { float c = ocho[l * 64 + i]; v += c * c; }
            M[i * 65 + j] = v;
        }
    }
    b[tid] = g_fmu[tid] - omu[l * 64 + tid];
    __syncthreads();
    for (int k = 0; k < 64; k++) {
        float p = sqrtf(M[k * 65 + k]);
        float pinv = 1.f / p;
        if (tid == 0) ld[k] = p;
        if (tid > k)       M[tid * 65 + k] *= pinv;
        else if (tid == k) b[k] *= pinv;
        __syncthreads();
        if (tid > k) {
            float c = M[tid * 65 + k];
            b[tid] -= c * b[k];
            for (int j = k + 1; j <= tid; j++) M[tid * 65 + j] -= c * M[j * 65 + k];
        }
        __syncthreads();
    }
    sred[tid] = 2.f * __logf(ld[tid]) + b[tid] * b[tid];
    __syncthreads();
    if (tid < 32) {
        float v = sred[tid] + sred[tid + 32];
#pragma unroll
        for (int o = 16; o; o >>= 1) v += __shfl_down_sync(0xffffffffu, v, o);
        if (tid == 0) out[l] = -0.5f * (64.f * LOG2PI_F + v) + g_fscore;
    }
}

// ---------------- launch ----------------
extern "C" void kernel_launch(void* const* d_in, const int* in_sizes, int n_in,
                              void* d_out, int out_size) {
    // metadata order: sentence, slen, input_mu_emb, input_cho_emb, trans_mu, trans_cho,
    //                 output_mu, output_cho. Defensive in case scalar slen is omitted.
    const int* sentence = (const int*)d_in[0];
    const int* slen_p   = nullptr;
    int base = 1;
    if (n_in >= 8) { slen_p = (const int*)d_in[1]; base = 2; }
    const float* imu  = (const float*)d_in[base + 0];
    const float* icho = (const float*)d_in[base + 1];
    const float* tmu  = (const float*)d_in[base + 2];
    const float* tcho = (const float*)d_in[base + 3];
    const float* omu  = (const float*)d_in[base + 4];
    const float* ocho = (const float*)d_in[base + 5];
    float* out = (float*)d_out;
    int slen_fb = in_sizes[0];

    prep_kernel<<<64, 256>>>(tcho);
    scan_kernel<<<1, 256>>>(sentence, slen_p, slen_fb, imu, icho, tmu);
    decode_kernel<<<out_size, 64>>>(omu, ocho, out);
}

// round 5
// speedup vs baseline: 3.5847x; 3.5847x over previous
#include <cuda_runtime.h>
#include <math.h>

#define LOG2PI_F 1.83787706640934548356f
#define MS 72   // M row stride (floats): 16B-aligned rows, cols kb/j0 multiples of 4
#define WS 68   // W row stride (floats): 16B-aligned rows

// ---------------- device-global scratch (no allocations allowed) ----------------
__device__ __align__(16) float g_Saa[64 * 64];
__device__ __align__(16) float g_Sab[64 * 64];
__device__ __align__(16) float g_Sbb[64 * 64];
__device__ float g_fmu[64];
__device__ float g_fvar[64 * 64];
__device__ float g_fscore;

// ---------------- prep: trans_var = C^T C, split into blocks ----------------
__global__ void prep_kernel(const float* __restrict__ C) {
    int idx = blockIdx.x * blockDim.x + threadIdx.x;
    if (idx >= 128 * 128) return;
    int i = idx >> 7, j = idx & 127;
    float s = 0.f;
#pragma unroll 8
    for (int k = 0; k < 128; k++) s += C[k * 128 + i] * C[k * 128 + j];
    if (i < 64) {
        if (j < 64) g_Saa[i * 64 + j] = s;
        else        g_Sab[i * 64 + (j - 64)] = s;
    } else if (j >= 64) {
        g_Sbb[(i - 64) * 64 + (j - 64)] = s;
    }
}

// ---------------- blocked Cholesky (rank-8) + forward substitution ----------------
// M: 64 x MS, lower triangle = SPD input; overwritten by true L (scaled, diag = L_kk).
// W: 64 x WS, cols 0..63 = RHS block, col 64 = RHS vector; overwritten by Z = L^-1 W.
// ldiag[k] = L_kk, idg[k] = 1/L_kk.
// TRI=true: RHS block starts as diag(d); Z stays exactly lower-triangular; only the
// active column front (cols < 8*(b+1)) plus col 64 is solved/updated per block.
// 3 __syncthreads per block (24 per factorization).
template <bool TRI>
__device__ __forceinline__ void chol64b(float* M, float* W, float* ldiag, float* idg, int tid) {
#pragma unroll 1
    for (int b = 0; b < 8; b++) {
        const int kb = b << 3;
        // ---- phase 1: 8x8 diagonal block, lanes 0..7 of warp 0, shuffle-based ----
        if (tid < 8) {
            const int r = tid;
            float d[8];
#pragma unroll
            for (int c = 0; c < 8; c++) d[c] = M[(kb + r) * MS + kb + c];
            float myrp = 0.f;
#pragma unroll
            for (int c = 0; c < 8; c++) {
                float piv = __shfl_sync(0xffu, d[c], c);
                float rp = rsqrtf(piv);          // MUFU.RSQ: fast, ~2 ulp
                float l = d[c] * rp;             // lane r>=c: L[r][c]; lane c: L_cc
                d[c] = l;
                if (c == r) myrp = rp;           // 1/L_cc for this lane's pivot
#pragma unroll
                for (int cc = c + 1; cc < 8; cc++)
                    d[cc] -= l * __shfl_sync(0xffu, l, cc);
            }
#pragma unroll
            for (int c = 0; c < 8; c++)
                if (c <= r) M[(kb + r) * MS + kb + c] = d[c];
            ldiag[kb + r] = d[r];
            idg[kb + r] = myrp;
        }
        __syncthreads();

        const int ni = 56 - kb;                   // trailing rows (kb+8..63)
        const int ncols = TRI ? (kb + 9) : 65;    // active W cols incl. vector col
        // ---- phase 2: panel solve (thread-per-row) + W row solve (thread-per-col) ----
        if (tid < ni) {
            const int i = kb + 8 + tid;
            float p[8];
#pragma unroll
            for (int c = 0; c < 8; c++) p[c] = M[i * MS + kb + c];
#pragma unroll
            for (int c = 0; c < 8; c++) {
                float s = p[c];
#pragma unroll
                for (int d2 = 0; d2 < 8; d2++)
                    if (d2 < c) s -= p[d2] * M[(kb + c) * MS + kb + d2];
                p[c] = s * idg[kb + c];
            }
#pragma unroll
            for (int c = 0; c < 8; c++) M[i * MS + kb + c] = p[c];
        } else if (tid >= 64 && tid < 64 + ncols) {
            const int q = tid - 64;
            const int j = (q == ncols - 1) ? 64 : q;
            float w[8];
#pragma unroll
            for (int c = 0; c < 8; c++) w[c] = W[(kb + c) * WS + j];
#pragma unroll
            for (int c = 0; c < 8; c++) {
                float s = w[c];
#pragma unroll
                for (int d2 = 0; d2 < 8; d2++)
                    if (d2 < c) s -= w[d2] * M[(kb + c) * MS + kb + d2];
                w[c] = s * idg[kb + c];
            }
#pragma unroll
            for (int c = 0; c < 8; c++) W[(kb + c) * WS + j] = w[c];
        }
        __syncthreads();

        // ---- phase 3: rank-8 trailing update, 4x4 register tiles, float4 SMEM ----
        if (b < 7) {
            const int m = ni;
            const int mt = m >> 2;
            const int nMt = (mt * (mt + 1)) >> 1;           // lower tiles of trailing M
            const int nreg = TRI ? (kb + 8) : 64;           // active regular W cols
            const int wct = nreg >> 2;
            const int nWt = mt * wct;
            const int total = nMt + nWt + mt;               // + mt col-64 vector units
            for (int u = tid; u < total; u += 256) {
                if (u < nMt) {
                    // decode triangular tile index (fast approx sqrt + correction)
                    float xf = 8.f * (float)u + 1.f;
                    int ti = (int)((xf * rsqrtf(xf) - 1.f) * 0.5f);
                    while ((ti + 1) * (ti + 2) / 2 <= u) ++ti;
                    while (ti * (ti + 1) / 2 > u) --ti;
                    int tj = u - ((ti * (ti + 1)) >> 1);
                    int i0 = kb + 8 + (ti << 2), j0 = kb + 8 + (tj << 2);
                    float a[4][8], bb[4][8];
#pragma unroll
                    for (int r = 0; r < 4; r++) {
                        *(float4*)&a[r][0] = *(const float4*)&M[(i0 + r) * MS + kb];
                        *(float4*)&a[r][4] = *(const float4*)&M[(i0 + r) * MS + kb + 4];
                        *(float4*)&bb[r][0] = *(const float4*)&M[(j0 + r) * MS + kb];
                        *(float4*)&bb[r][4] = *(const float4*)&M[(j0 + r) * MS + kb + 4];
                    }
                    float acc[4][4];
#pragma unroll
                    for (int r = 0; r < 4; r++)
#pragma unroll
                        for (int qq = 0; qq < 4; qq++) acc[r][qq] = 0.f;
#pragma unroll
                    for (int c = 0; c < 8; c++)
#pragma unroll
                        for (int r = 0; r < 4; r++)
#pragma unroll
                            for (int qq = 0; qq < 4; qq++)
                                acc[r][qq] += a[r][c] * bb[qq][c];
#pragma unroll
                    for (int r = 0; r < 4; r++) {
                        float4 mv = *(const float4*)&M[(i0 + r) * MS + j0];
                        mv.x -= acc[r][0]; mv.y -= acc[r][1];
                        mv.z -= acc[r][2]; mv.w -= acc[r][3];
                        *(float4*)&M[(i0 + r) * MS + j0] = mv;
                    }
                } else if (u < nMt + nWt) {
                    int u2 = u - nMt;
                    int ti = u2 / wct, tj = u2 - ti * wct;
                    int i0 = kb + 8 + (ti << 2), j0 = tj << 2;
                    float a[4][8], ws[8][4];
#pragma unroll
                    for (int r = 0; r < 4; r++) {
                        *(float4*)&a[r][0] = *(const float4*)&M[(i0 + r) * MS + kb];
                        *(float4*)&a[r][4] = *(const float4*)&M[(i0 + r) * MS + kb + 4];
                    }
#pragma unroll
                    for (int c = 0; c < 8; c++)
                        *(float4*)&ws[c][0] = *(const float4*)&W[(kb + c) * WS + j0];
                    float acc[4][4];
#pragma unroll
                    for (int r = 0; r < 4; r++)
#pragma unroll
                        for (int qq = 0; qq < 4; qq++) acc[r][qq] = 0.f;
#pragma unroll
                    for (int c = 0; c < 8; c++)
#pragma unroll
                        for (int r = 0; r < 4; r++)
#pragma unroll
                            for (int qq = 0; qq < 4; qq++)
                                acc[r][qq] += a[r][c] * ws[c][qq];
#pragma unroll
                    for (int r = 0; r < 4; r++) {
                        float4 wv = *(const float4*)&W[(i0 + r) * WS + j0];
                        wv.x -= acc[r][0]; wv.y -= acc[r][1];
                        wv.z -= acc[r][2]; wv.w -= acc[r][3];
                        *(float4*)&W[(i0 + r) * WS + j0] = wv;
                    }
                } else {
                    int u3 = u - nMt - nWt;
                    int i0 = kb + 8 + (u3 << 2);
                    float a[4][8], wc[8], av[4];
#pragma unroll
                    for (int r = 0; r < 4; r++) {
                        *(float4*)&a[r][0] = *(const float4*)&M[(i0 + r) * MS + kb];
                        *(float4*)&a[r][4] = *(const float4*)&M[(i0 + r) * MS + kb + 4];
                        av[r] = 0.f;
                    }
#pragma unroll
                    for (int c = 0; c < 8; c++) wc[c] = W[(kb + c) * WS + 64];
#pragma unroll
                    for (int c = 0; c < 8; c++)
#pragma unroll
                        for (int r = 0; r < 4; r++) av[r] += a[r][c] * wc[c];
#pragma unroll
                    for (int r = 0; r < 4; r++) W[(i0 + r) * WS + 64] -= av[r];
                }
            }
        }
        __syncthreads();
    }
}

// ---------------- lower-triangle SYRK: M(lower) = gAdd (+diag dd) - Z^T Z ----------------
// 4x4 register tiles over the 136 lower tiles; float4 SMEM loads; no syncs inside.
__device__ __forceinline__ void syrk_lower(float* M, const float* W,
                                           const float* __restrict__ gAdd,
                                           const float* dd, int tid, bool tri) {
    if (tid < 136) {
        float xf = 8.f * (float)tid + 1.f;
        int ti = (int)((xf * rsqrtf(xf) - 1.f) * 0.5f);
        while ((ti + 1) * (ti + 2) / 2 <= tid) ++ti;
        while (ti * (ti + 1) / 2 > tid) --ti;
        int tj = tid - ((ti * (ti + 1)) >> 1);
        int i0 = ti << 2, j0 = tj << 2;
        float acc[4][4];
#pragma unroll
        for (int r = 0; r < 4; r++)
#pragma unroll
            for (int q = 0; q < 4; q++) acc[r][q] = 0.f;
        int k0 = tri ? i0 : 0;  // Z lower-triangular: rows k < i0 are exact zero in cols >= i0
#pragma unroll 4
        for (int k = k0; k < 64; k++) {
            const float* Wr = W + k * WS;
            float4 av = *(const float4*)&Wr[i0];
            float4 bv = *(const float4*)&Wr[j0];
            float a0 = av.x, a1 = av.y, a2 = av.z, a3 = av.w;
            float b0 = bv.x, b1 = bv.y, b2 = bv.z, b3 = bv.w;
            acc[0][0] += a0 * b0; acc[0][1] += a0 * b1; acc[0][2] += a0 * b2; acc[0][3] += a0 * b3;
            acc[1][0] += a1 * b0; acc[1][1] += a1 * b1; acc[1][2] += a1 * b2; acc[1][3] += a1 * b3;
            acc[2][0] += a2 * b0; acc[2][1] += a2 * b1; acc[2][2] += a2 * b2; acc[2][3] += a2 * b3;
            acc[3][0] += a3 * b0; acc[3][1] += a3 * b1; acc[3][2] += a3 * b2; acc[3][3] += a3 * b3;
        }
#pragma unroll
        for (int r = 0; r < 4; r++) {
            float4 g = *(const float4*)&gAdd[(i0 + r) * 64 + j0];
            float v[4] = { g.x - acc[r][0], g.y - acc[r][1], g.z - acc[r][2], g.w - acc[r][3] };
            if (dd && ti == tj) v[r] += dd[i0 + r];   // diagonal lives at col r of diag tiles
            float4 o; o.x = v[0]; o.y = v[1]; o.z = v[2]; o.w = v[3];
            *(float4*)&M[(i0 + r) * MS + j0] = o;      // upper-of-diag junk never read
        }
    }
}

// ---------------- transition phase (also used for the initial integral) ----------------
// Entry: M(lower) = lam = Saa + var_e; me = emission mean (0 for init).
// Exit: M(lower) = var_t, mu = mu_t, score accumulated into *s_acc.
__device__ __forceinline__ void transition_phase(float* M, float* W, float* mu,
                                                 const float* me, float* ldiag, float* idg,
                                                 float* sred, float* s_acc,
                                                 const float* tmu_s, int tid) {
    {   // W = Sab (float4 copy), each thread: one row-quarter
        int i = tid >> 2, q = tid & 3;
#pragma unroll
        for (int c = 0; c < 4; c++) {
            int jb = q * 16 + (c << 2);
            *(float4*)&W[i * WS + jb] = *(const float4*)&g_Sab[i * 64 + jb];
        }
    }
    if (tid < 64) W[tid * WS + 64] = me[tid] - tmu_s[tid];
    __syncthreads();
    chol64b<false>(M, W, ldiag, idg, tid);
    if (tid < 64) {
        float z = W[tid * WS + 64];
        sred[tid] = 2.f * __logf(ldiag[tid]) + z * z;
        float acc = 0.f;
#pragma unroll 4
        for (int k = 0; k < 64; k++) acc += W[k * WS + tid] * W[k * WS + 64];
        mu[tid] = tmu_s[64 + tid] + acc;               // mu_t = mu_b + U^T z2
    }
    syrk_lower(M, W, g_Sbb, nullptr, tid, false);      // var_t = Sbb - U^T U
    __syncthreads();
    if (tid < 32) {
        float v = sred[tid] + sred[tid + 32];
#pragma unroll
        for (int o = 16; o; o >>= 1) v += __shfl_down_sync(0xffffffffu, v, o);
        if (tid == 0) *s_acc += -0.5f * (64.f * LOG2PI_F + v);
    }
}

// ---------------- the sequential scan: one persistent CTA ----------------
__global__ void __launch_bounds__(256, 1)
scan_kernel(const int* __restrict__ sentence, const int* __restrict__ slen_p, int slen_fb,
            const float* __restrict__ imu_emb, const float* __restrict__ icho_emb,
            const float* __restrict__ tmu) {
    __shared__ __align__(16) float M[64 * MS];
    __shared__ __align__(16) float W[64 * WS];
    __shared__ float mu[64], me[64], mm[64], dd[64];
    __shared__ float ldiag[64], idg[64], sred[64], tmu_s[128];
    __shared__ float s_acc;

    int tid = threadIdx.x;
    int slen = slen_p ? slen_p[0] : slen_fb;

    // ---- init: M = Saa + I (full rows), me = 0, s_acc = 0, cache tmu ----
    if (tid == 0) s_acc = 0.f;
    if (tid < 64) me[tid] = 0.f;
    if (tid < 128) tmu_s[tid] = tmu[tid];
    {
        int i = tid >> 2, q = tid & 3;
#pragma unroll
        for (int c = 0; c < 4; c++) {
            int jb = q * 16 + (c << 2);
            float4 v = *(const float4*)&g_Saa[i * 64 + jb];
            if (i >= jb && i < jb + 4) ((float*)&v)[i - jb] += 1.f;
            *(float4*)&M[i * MS + jb] = v;
        }
    }
    __syncthreads();
    transition_phase(M, W, mu, me, ldiag, idg, sred, &s_acc, tmu_s, tid);  // (s0, m0, v0)

    // ---- sequential steps ----
    for (int t = 0; t < slen; t++) {
        // -------- emission --------
        if (tid < 64) {
            int tok = sentence[t];
            mm[tid] = imu_emb[tok * 64 + tid];
            float c = icho_emb[tok * 64 + tid];
            dd[tid] = c * c;
        }
        __syncthreads();
        if (tid < 64) M[tid * MS + tid] += dd[tid];   // vs = var_prev + diag(d), in place
        {   // W = diag(d) in cols 0..63 (exact zeros elsewhere)
            int i = tid >> 2, q = tid & 3;
#pragma unroll
            for (int c = 0; c < 4; c++) {
                int jb = q * 16 + (c << 2);
                float4 v; v.x = 0.f; v.y = 0.f; v.z = 0.f; v.w = 0.f;
                if (i >= jb && i < jb + 4) ((float*)&v)[i - jb] = dd[i];
                *(float4*)&W[i * WS + jb] = v;
            }
        }
        if (tid < 64) W[tid * WS + 64] = mu[tid] - mm[tid];
        __syncthreads();
        chol64b<true>(M, W, ldiag, idg, tid);          // L(vs); Z = L^-1 diag(d); z = L^-1(mu-m)
        if (tid < 64) {
            float z = W[tid * WS + 64];
            sred[tid] = 2.f * __logf(ldiag[tid]) + z * z;
            float acc = 0.f;
#pragma unroll 4
            for (int k = tid; k < 64; k++) acc += W[k * WS + tid] * W[k * WS + 64];
            me[tid] = mm[tid] + acc;                   // mu_e = m + Z^T z
        }
        syrk_lower(M, W, g_Saa, dd, tid, true);        // lam = Saa + diag(d) - Z^T Z
        __syncthreads();
        if (tid < 32) {
            float v = sred[tid] + sred[tid + 32];
#pragma unroll
            for (int o = 16; o; o >>= 1) v += __shfl_down_sync(0xffffffffu, v, o);
            if (tid == 0) s_acc += -0.5f * (64.f * LOG2PI_F + v);
        }
        // -------- transition --------
        transition_phase(M, W, mu, me, ldiag, idg, sred, &s_acc, tmu_s, tid);
    }

    // ---- publish carry ----
    if (tid < 64) g_fmu[tid] = mu[tid];
    for (int n = tid; n < 4096; n += 256) {
        int i = n >> 6, j = n & 63;
        if (j <= i) g_fvar[n] = M[i * MS + j];
    }
    if (tid == 0) g_fscore = s_acc;
}

// ---------------- decode: 50 independent small Choleskys ----------------
__global__ void decode_kernel(const float* __restrict__ omu, const float* __restrict__ ocho,
                              float* __restrict__ out) {
    __shared__ float M[64 * 65];
    __shared__ float b[64];
    __shared__ float ld[64];
    __shared__ float sred[64];
    int l = blockIdx.x, tid = threadIdx.x;  // 64 threads
    for (int n = tid; n < 4096; n += 64) {
        int i = n >> 6, j = n & 63;
        if (j <= i) {
            float v = g_fvar[n];
            if (i == j) { float c = ocho[l * 64 + i]; v += c * c; }
            M[i * 65 + j] = v;
        }
    }
    b[tid] = g_fmu[tid] - omu[l * 64 + tid];
    __syncthreads();
    for (int k = 0; k < 64; k++) {
        float rp = rsqrtf(M[k * 65 + k]);
        if (tid == 0) ld[k] = M[k * 65 + k] * rp;
        if (tid > k)       M[tid * 65 + k] *= rp;
        else if (tid == k) b[k] *= rp;
        __syncthreads();
        if (tid > k) {
            float c = M[tid * 65 + k];
            b[tid] -= c * b[k];
            for (int j = k + 1; j <= tid; j++) M[tid * 65 + j] -= c * M[j * 65 + k];
        }
        __syncthreads();
    }
    sred[tid] = 2.f * __logf(ld[tid]) + b[tid] * b[tid];
    __syncthreads();
    if (tid < 32) {
        float v = sred[tid] + sred[tid + 32];
#pragma unroll
        for (int o = 16; o; o >>= 1) v += __shfl_down_sync(0xffffffffu, v, o);
        if (tid == 0) out[l] = -0.5f * (64.f * LOG2PI_F + v) + g_fscore;
    }
}

// ---------------- launch ----------------
extern "C" void kernel_launch(void* const* d_in, const int* in_sizes, int n_in,
                              void* d_out, int out_size) {
    const int* sentence = (const int*)d_in[0];
    const int* slen_p   = nullptr;
    int base = 1;
    if (n_in >= 8) { slen_p = (const int*)d_in[1]; base = 2; }
    const float* imu  = (const float*)d_in[base + 0];
    const float* icho = (const float*)d_in[base + 1];
    const float* tmu  = (const float*)d_in[base + 2];
    const float* tcho = (const float*)d_in[base + 3];
    const float* omu  = (const float*)d_in[base + 4];
    const float* ocho = (const float*)d_in[base + 5];
    float* out = (float*)d_out;
    int slen_fb = in_sizes[0];

    prep_kernel<<<64, 256>>>(tcho);
    scan_kernel<<<1, 256>>>(sentence, slen_p, slen_fb, imu, icho, tmu);
    decode_kernel<<<out_size, 64>>>(omu, ocho, out);
}